// round 13
// baseline (speedup 1.0000x reference)
#include <cuda_runtime.h>
#include <cuda_fp16.h>
#include <cstdint>
#include <math.h>

#define BATCH 4
#define CH    512
#define HW    4096
#define NG    32

static const size_t SFE = (size_t)CH * HW;

// ================= scratch (device globals) =================
__device__ __half g_xnT[(size_t)BATCH * HW * CH];   // (i,c) fp16
__device__ __half g_q16[(size_t)BATCH * HW * CH];   // (i,c)
__device__ __half g_k16[(size_t)BATCH * HW * CH];   // (i,c)
__device__ __half g_v16[(size_t)BATCH * CH * HW];   // (c,i)
__device__ __half g_s16[(size_t)BATCH * HW * HW];   // scores fp16
__device__ __half g_P16[(size_t)BATCH * HW * HW];   // probs fp16
__device__ __half g_ot [(size_t)BATCH * HW * CH];   // (i,c)
__device__ __half g_w16[(size_t)4 * CH * CH];       // q,k,v,o weights

// ================= helpers =================
__device__ __forceinline__ uint32_t smem_u32(const void* p) {
    uint32_t a;
    asm("{ .reg .u64 t; cvta.to.shared.u64 t, %1; cvt.u32.u64 %0, t; }"
        : "=r"(a) : "l"(p));
    return a;
}
__device__ __forceinline__ uint32_t pack2h(__half a, __half b) {
    return (uint32_t)__half_as_ushort(a) |
           ((uint32_t)__half_as_ushort(b) << 16);
}

#define LDSM4(R, a) \
    asm volatile("ldmatrix.sync.aligned.m8n8.x4.shared.b16 {%0,%1,%2,%3}, [%4];" \
        : "=r"((R)[0]), "=r"((R)[1]), "=r"((R)[2]), "=r"((R)[3]) : "r"(a))

__device__ __forceinline__ void mma_h(float* d, const uint32_t* a,
                                      const uint32_t* b) {
    asm volatile(
        "mma.sync.aligned.m16n8k16.row.col.f32.f16.f16.f32 "
        "{%0,%1,%2,%3}, {%4,%5,%6,%7}, {%8,%9}, {%0,%1,%2,%3};"
        : "+f"(d[0]), "+f"(d[1]), "+f"(d[2]), "+f"(d[3])
        : "r"(a[0]), "r"(a[1]), "r"(a[2]), "r"(a[3]), "r"(b[0]), "r"(b[1]));
}
// fp16-accumulate variant: d = 2 x f16x2 regs
__device__ __forceinline__ void mma_h16(uint32_t* d, const uint32_t* a,
                                        const uint32_t* b) {
    asm volatile(
        "mma.sync.aligned.m16n8k16.row.col.f16.f16.f16.f16 "
        "{%0,%1}, {%2,%3,%4,%5}, {%6,%7}, {%0,%1};"
        : "+r"(d[0]), "+r"(d[1])
        : "r"(a[0]), "r"(a[1]), "r"(a[2]), "r"(a[3]), "r"(b[0]), "r"(b[1]));
}

// smem: 2 matrices (A, B) of 128 rows x 32 halves padded to 80B rows; 2 stages.
#define ROWB   80
#define MATB   10240
#define STAGEB (2 * MATB)
#define SM_BYTES (2 * STAGEB)
#define THREADS 512
// av kernel: stages + fp32 shadow accumulator (32 slots x 512 threads)
#define AV_SHADOW_OFF (2 * STAGEB)
#define AV_SMEM (2 * STAGEB + 32 * THREADS * 4)

// ============================================================
// fp16 GEMM (fp32 accum) via mma.sync + ldmatrix. 16 warps, 32x32 warp tile.
// OUTM: 0 = fp32 [+bias/res], 2 = fp16.
// ============================================================
template<int OUTM, bool BROW, bool BCOL, bool RES>
__device__ __forceinline__ void tgemm(
    const __half* __restrict__ A, int lda,
    const __half* __restrict__ B, int ldb,
    int K, float alpha,
    const float* __restrict__ bias_row, const float* __restrict__ bias_col,
    const float* __restrict__ res, int ldr,
    float* __restrict__ Cf, __half* __restrict__ Ch, int ldc)
{
    extern __shared__ char smem[];
    const uint32_t sb = smem_u32(smem);
    const int tid  = threadIdx.x;
    const int wid  = tid >> 5, lane = tid & 31;
    const int mw   = wid >> 2, nw = wid & 3;
    const int m0   = blockIdx.y * 128, n0 = blockIdx.x * 128;
    const int C    = K >> 5;

    float acc[2][4][4];
    #pragma unroll
    for (int i = 0; i < 2; i++)
        #pragma unroll
        for (int j = 0; j < 4; j++)
            #pragma unroll
            for (int q = 0; q < 4; q++) acc[i][j][q] = 0.f;

    auto load_chunk = [&](int ck) {
        const uint32_t stage = sb + (ck & 1) * STAGEB;
        #pragma unroll
        for (int i = 0; i < 2; i++) {
            const int unit = tid + THREADS * i;
            const int mat = unit >> 9;
            const int row = (unit >> 2) & 127;
            const int u   = unit & 3;
            const __half* src = (mat == 0) ? A : B;
            const int ld_ = (mat == 0) ? lda : ldb;
            const int r0  = (mat == 0) ? m0  : n0;
            const char* gsrc =
                (const char*)(src + (size_t)(r0 + row) * ld_ + ck * 32) + u * 16;
            const uint32_t dst = stage + mat * MATB + row * ROWB + u * 16;
            asm volatile("cp.async.cg.shared.global [%0], [%1], 16;"
                         :: "r"(dst), "l"(gsrc));
        }
        asm volatile("cp.async.commit_group;" ::: "memory");
    };

    load_chunk(0);

    const int gq = lane >> 2, qt = lane & 3;
    const int lnA_row = lane & 15;
    const int lnA_off = (lane >> 4) << 4;
    const int lnB_row = (lane & 7) + ((lane & 16) >> 1);
    const int lnB_off = (lane & 8) << 1;

    for (int c = 0; c < C; c++) {
        if (c + 1 < C) load_chunk(c + 1);
        if (c + 1 < C) asm volatile("cp.async.wait_group 1;" ::: "memory");
        else           asm volatile("cp.async.wait_group 0;" ::: "memory");
        __syncthreads();

        const uint32_t stage = sb + (c & 1) * STAGEB;

        #pragma unroll
        for (int ks = 0; ks < 2; ks++) {
            const uint32_t ko = ks * 32;
            uint32_t ah[2][4];
            #pragma unroll
            for (int mt = 0; mt < 2; mt++) {
                const uint32_t aAddr = stage +
                    (mw * 32 + mt * 16 + lnA_row) * ROWB + ko + lnA_off;
                LDSM4(ah[mt], aAddr);
            }
            #pragma unroll
            for (int p = 0; p < 2; p++) {
                const uint32_t bAddr = stage + MATB +
                    (nw * 32 + p * 16 + lnB_row) * ROWB + ko + lnB_off;
                uint32_t bh[4];
                LDSM4(bh, bAddr);
                #pragma unroll
                for (int half_ = 0; half_ < 2; half_++) {
                    const int nt = p * 2 + half_;
                    #pragma unroll
                    for (int mt = 0; mt < 2; mt++)
                        mma_h(acc[mt][nt], ah[mt], bh + half_ * 2);
                }
            }
        }
        __syncthreads();
    }

    #pragma unroll
    for (int mt = 0; mt < 2; mt++) {
        const int mA = m0 + mw * 32 + mt * 16 + gq;
        #pragma unroll
        for (int half_ = 0; half_ < 2; half_++) {
            const int m = mA + half_ * 8;
            const float br = BROW ? bias_row[m] : 0.f;
            #pragma unroll
            for (int nt = 0; nt < 4; nt++) {
                const int n = n0 + nw * 32 + nt * 8 + qt * 2;
                float vx = acc[mt][nt][half_ * 2 + 0] * alpha + br;
                float vy = acc[mt][nt][half_ * 2 + 1] * alpha + br;
                if (BCOL) { vx += bias_col[n]; vy += bias_col[n + 1]; }
                if (RES) {
                    const float* rp = res + (size_t)m * ldr + n;
                    vx += rp[0]; vy += rp[1];
                }
                if (OUTM == 0) {
                    float2 o = {vx, vy};
                    *(float2*)(Cf + (size_t)m * ldc + n) = o;
                } else {
                    *(uint32_t*)(Ch + (size_t)m * ldc + n) =
                        pack2h(__float2half(vx), __float2half(vy));
                }
            }
        }
    }
}

// ================= wrapper kernels =================

__global__ __launch_bounds__(THREADS, 1) void tg_qk(
    const float* __restrict__ bq, const float* __restrict__ bk)
{
    const int b = blockIdx.z >> 1, s = blockIdx.z & 1;
    __half* Cq = (s == 0 ? g_q16 : g_k16) + (size_t)b * HW * CH;
    tgemm<2, false, true, false>(
        g_xnT + (size_t)b * HW * CH, CH,
        g_w16 + (size_t)s * CH * CH, CH,
        CH, 1.f, nullptr, (s == 0 ? bq : bk), nullptr, 0,
        nullptr, Cq, CH);
}

__global__ __launch_bounds__(THREADS, 1) void tg_v(const float* __restrict__ bv)
{
    const int b = blockIdx.z;
    tgemm<2, true, false, false>(
        g_w16 + (size_t)2 * CH * CH, CH,
        g_xnT + (size_t)b * HW * CH, CH,
        CH, 1.f, bv, nullptr, nullptr, 0,
        nullptr, g_v16 + (size_t)b * CH * HW, HW);
}

__global__ __launch_bounds__(THREADS, 1) void tg_score()
{
    const int b = blockIdx.z;
    tgemm<2, false, false, false>(
        g_q16 + (size_t)b * HW * CH, CH,
        g_k16 + (size_t)b * HW * CH, CH,
        CH, 0.044194173824159216f, nullptr, nullptr, nullptr, 0,
        nullptr, g_s16 + (size_t)b * HW * HW, HW);
}

// ================= av: fp16-accumulate + fp32 smem shadow =================
// Ot(128x128 tile of (i,c)) = P16(i,:) . v16(c,:)^T, K = HW = 4096.
// f16 acc over 8-chunk (256-K) windows, promoted to fp32 shadow in smem.
__global__ __launch_bounds__(THREADS, 1) void tg_av()
{
    extern __shared__ char smem[];
    const uint32_t sb = smem_u32(smem);
    float* shadow = (float*)(smem + AV_SHADOW_OFF);
    const int tid  = threadIdx.x;
    const int wid  = tid >> 5, lane = tid & 31;
    const int mw   = wid >> 2, nw = wid & 3;
    const int m0   = blockIdx.y * 128, n0 = blockIdx.x * 128;
    const int b    = blockIdx.z;
    const __half* A = g_P16 + (size_t)b * HW * HW;  const int lda = HW;
    const __half* B = g_v16 + (size_t)b * CH * HW;  const int ldb = HW;
    __half* Ch = g_ot + (size_t)b * HW * CH;        const int ldc = CH;
    const int C = HW >> 5;   // 128 chunks

    #pragma unroll
    for (int i = 0; i < 32; i++) shadow[i * THREADS + tid] = 0.f;

    uint32_t acc16[2][4][2];
    #pragma unroll
    for (int i = 0; i < 2; i++)
        #pragma unroll
        for (int j = 0; j < 4; j++) { acc16[i][j][0] = 0u; acc16[i][j][1] = 0u; }

    auto load_chunk = [&](int ck) {
        const uint32_t stage = sb + (ck & 1) * STAGEB;
        #pragma unroll
        for (int i = 0; i < 2; i++) {
            const int unit = tid + THREADS * i;
            const int mat = unit >> 9;
            const int row = (unit >> 2) & 127;
            const int u   = unit & 3;
            const __half* src = (mat == 0) ? A : B;
            const int ld_ = (mat == 0) ? lda : ldb;
            const int r0  = (mat == 0) ? m0  : n0;
            const char* gsrc =
                (const char*)(src + (size_t)(r0 + row) * ld_ + ck * 32) + u * 16;
            const uint32_t dst = stage + mat * MATB + row * ROWB + u * 16;
            asm volatile("cp.async.cg.shared.global [%0], [%1], 16;"
                         :: "r"(dst), "l"(gsrc));
        }
        asm volatile("cp.async.commit_group;" ::: "memory");
    };

    load_chunk(0);

    const int gq = lane >> 2, qt = lane & 3;
    const int lnA_row = lane & 15;
    const int lnA_off = (lane >> 4) << 4;
    const int lnB_row = (lane & 7) + ((lane & 16) >> 1);
    const int lnB_off = (lane & 8) << 1;

    for (int c = 0; c < C; c++) {
        if (c + 1 < C) load_chunk(c + 1);
        if (c + 1 < C) asm volatile("cp.async.wait_group 1;" ::: "memory");
        else           asm volatile("cp.async.wait_group 0;" ::: "memory");
        __syncthreads();

        const uint32_t stage = sb + (c & 1) * STAGEB;

        #pragma unroll
        for (int ks = 0; ks < 2; ks++) {
            const uint32_t ko = ks * 32;
            uint32_t ah[2][4];
            #pragma unroll
            for (int mt = 0; mt < 2; mt++) {
                const uint32_t aAddr = stage +
                    (mw * 32 + mt * 16 + lnA_row) * ROWB + ko + lnA_off;
                LDSM4(ah[mt], aAddr);
            }
            #pragma unroll
            for (int p = 0; p < 2; p++) {
                const uint32_t bAddr = stage + MATB +
                    (nw * 32 + p * 16 + lnB_row) * ROWB + ko + lnB_off;
                uint32_t bh[4];
                LDSM4(bh, bAddr);
                #pragma unroll
                for (int half_ = 0; half_ < 2; half_++) {
                    const int nt = p * 2 + half_;
                    #pragma unroll
                    for (int mt = 0; mt < 2; mt++)
                        mma_h16(acc16[mt][nt], ah[mt], bh + half_ * 2);
                }
            }
        }

        if ((c & 7) == 7) {      // promote 256-K window to fp32 shadow
            #pragma unroll
            for (int mt = 0; mt < 2; mt++)
                #pragma unroll
                for (int nt = 0; nt < 4; nt++)
                    #pragma unroll
                    for (int r = 0; r < 2; r++) {
                        float2 f = __half22float2(*(__half2*)&acc16[mt][nt][r]);
                        const int s0 = ((mt * 4 + nt) * 4 + r * 2) * THREADS + tid;
                        shadow[s0]           += f.x;
                        shadow[s0 + THREADS] += f.y;
                        acc16[mt][nt][r] = 0u;
                    }
        }
        __syncthreads();
    }

    // ---- epilogue from shadow ----
    #pragma unroll
    for (int mt = 0; mt < 2; mt++) {
        const int mA = m0 + mw * 32 + mt * 16 + gq;
        #pragma unroll
        for (int half_ = 0; half_ < 2; half_++) {
            const int m = mA + half_ * 8;
            #pragma unroll
            for (int nt = 0; nt < 4; nt++) {
                const int n = n0 + nw * 32 + nt * 8 + qt * 2;
                const int s0 = ((mt * 4 + nt) * 4 + half_ * 2) * THREADS + tid;
                float vx = shadow[s0];
                float vy = shadow[s0 + THREADS];
                *(uint32_t*)(Ch + (size_t)m * ldc + n) =
                    pack2h(__float2half(vx), __float2half(vy));
            }
        }
    }
}

__global__ __launch_bounds__(THREADS, 1) void tg_out(
    const float* __restrict__ bo, const float* __restrict__ x,
    float* __restrict__ out)
{
    const int b = blockIdx.z;
    tgemm<0, true, false, true>(
        g_w16 + (size_t)3 * CH * CH, CH,
        g_ot + (size_t)b * HW * CH, CH,
        CH, 1.f, bo, nullptr, x + (size_t)b * SFE, HW,
        out + (size_t)b * SFE, nullptr, HW);
}

// ================= fused GroupNorm + transpose + fp16 =================
// One block per (batch, group): 16 ch x 4096. Writes g_xnT (i,c) fp16 directly.
__global__ __launch_bounds__(256) void gnx_kernel(
    const float* __restrict__ x, const float* __restrict__ gamma,
    const float* __restrict__ beta)
{
    const int bg = blockIdx.x;                 // b*32 + g
    const int b = bg >> 5, g = bg & 31;
    const size_t base = (size_t)bg * 16 * HW;
    const int n = 16 * HW;                     // 65536
    const int t = threadIdx.x;

    // ---- pass 1: stats ----
    const float4* xv = (const float4*)(x + base);
    float s = 0.f, ss = 0.f;
    for (int i = t; i < n / 4; i += 256) {
        float4 v = xv[i];
        s  += v.x + v.y + v.z + v.w;
        ss += v.x*v.x + v.y*v.y + v.z*v.z + v.w*v.w;
    }
    __shared__ float sh[64];
    #pragma unroll
    for (int o = 16; o > 0; o >>= 1) {
        s  += __shfl_xor_sync(~0u, s, o);
        ss += __shfl_xor_sync(~0u, ss, o);
    }
    const int warp = t >> 5, lane = t & 31;
    if (lane == 0) { sh[warp] = s; sh[32 + warp] = ss; }
    __syncthreads();
    if (warp == 0) {
        float a = (lane < 8) ? sh[lane] : 0.f;
        float bb = (lane < 8) ? sh[32 + lane] : 0.f;
        #pragma unroll
        for (int o = 4; o > 0; o >>= 1) {
            a  += __shfl_xor_sync(~0u, a, o);
            bb += __shfl_xor_sync(~0u, bb, o);
        }
        if (lane == 0) { sh[0] = a; sh[1] = bb; }
    }
    __syncthreads();
    const float mean = sh[0] / n;
    const float var  = sh[1] / n - mean * mean;
    const float inv  = rsqrtf(var + 1e-6f);
    const int gbase = g * 16;

    // ---- pass 2: normalize + transpose to (i,c) fp16 ----
    const int tc8 = (t >> 7) * 8;              // 0 or 8
    const int ti  = t & 127;
    float ga[8], be[8];
    #pragma unroll
    for (int q = 0; q < 8; q++) {
        ga[q] = gamma[gbase + tc8 + q] * inv;
        be[q] = beta[gbase + tc8 + q];
    }
    __shared__ float ts[16][129];
    for (int tile = 0; tile < 32; tile++) {
        const int i0 = tile * 128;
        #pragma unroll
        for (int j = 0; j < 8; j++) {
            const int idx = t + 256 * j;       // 0..2047
            const int c = idx >> 7, i = idx & 127;
            ts[c][i] = x[base + (size_t)c * HW + i0 + i];
        }
        __syncthreads();
        uint4 hv;
        uint32_t* hw_ = (uint32_t*)&hv;
        #pragma unroll
        for (int q2 = 0; q2 < 4; q2++) {
            const float v0 = (ts[tc8 + q2*2    ][ti] - mean) * ga[q2*2]     + be[q2*2];
            const float v1 = (ts[tc8 + q2*2 + 1][ti] - mean) * ga[q2*2 + 1] + be[q2*2 + 1];
            hw_[q2] = pack2h(__float2half(v0), __float2half(v1));
        }
        *(uint4*)(g_xnT + ((size_t)b * HW + i0 + ti) * CH + gbase + tc8) = hv;
        __syncthreads();
    }
}

// ================= weight convert =================
__global__ __launch_bounds__(256) void wconv_kernel(
    const float* __restrict__ wq, const float* __restrict__ wk,
    const float* __restrict__ wv, const float* __restrict__ wo)
{
    const size_t idx = (size_t)blockIdx.x * 256 + threadIdx.x;
    const int which = (int)(idx >> 18);
    const size_t off = idx & ((1 << 18) - 1);
    const float* w = (which == 0) ? wq : (which == 1) ? wk : (which == 2) ? wv : wo;
    g_w16[idx] = __float2half(w[off]);
}

// ================= softmax: fp16 in -> fp16 out =================
__global__ __launch_bounds__(256) void softmax_kernel()
{
    const size_t row = blockIdx.x;
    const uint2* pv = (const uint2*)(g_s16 + row * HW);
    __half* ph = g_P16 + row * HW;
    const int t = threadIdx.x;
    float v[4][4];
    float mx = -1e30f;
    #pragma unroll
    for (int j = 0; j < 4; j++) {
        uint2 u = pv[t + 256 * j];
        __half2 a = *(__half2*)&u.x, b = *(__half2*)&u.y;
        float2 fa = __half22float2(a), fb = __half22float2(b);
        v[j][0] = fa.x; v[j][1] = fa.y; v[j][2] = fb.x; v[j][3] = fb.y;
        mx = fmaxf(mx, fmaxf(fmaxf(v[j][0], v[j][1]), fmaxf(v[j][2], v[j][3])));
    }
    __shared__ float sh[8];
    #pragma unroll
    for (int o = 16; o > 0; o >>= 1) mx = fmaxf(mx, __shfl_xor_sync(~0u, mx, o));
    if ((t & 31) == 0) sh[t >> 5] = mx;
    __syncthreads();
    const float m0 = fmaxf(fmaxf(fmaxf(sh[0], sh[1]), fmaxf(sh[2], sh[3])),
                           fmaxf(fmaxf(sh[4], sh[5]), fmaxf(sh[6], sh[7])));
    __syncthreads();
    float sum = 0.f;
    #pragma unroll
    for (int j = 0; j < 4; j++) {
        #pragma unroll
        for (int q = 0; q < 4; q++) {
            v[j][q] = __expf(v[j][q] - m0);
            sum += v[j][q];
        }
    }
    #pragma unroll
    for (int o = 16; o > 0; o >>= 1) sum += __shfl_xor_sync(~0u, sum, o);
    if ((t & 31) == 0) sh[t >> 5] = sum;
    __syncthreads();
    const float tot = sh[0]+sh[1]+sh[2]+sh[3]+sh[4]+sh[5]+sh[6]+sh[7];
    const float inv = 1.f / tot;
    #pragma unroll
    for (int j = 0; j < 4; j++) {
        const int eo = (t + 256 * j) * 4;
        uint2 hv = { pack2h(__float2half(v[j][0] * inv), __float2half(v[j][1] * inv)),
                     pack2h(__float2half(v[j][2] * inv), __float2half(v[j][3] * inv)) };
        *(uint2*)(ph + eo) = hv;
    }
}

// ============================================================
extern "C" void kernel_launch(void* const* d_in, const int* in_sizes, int n_in,
                              void* d_out, int out_size)
{
    const float* x   = (const float*)d_in[0];
    const float* gnw = (const float*)d_in[1];
    const float* gnb = (const float*)d_in[2];
    const float* wq  = (const float*)d_in[3];
    const float* bq  = (const float*)d_in[4];
    const float* wk  = (const float*)d_in[5];
    const float* bk  = (const float*)d_in[6];
    const float* wv  = (const float*)d_in[7];
    const float* bv  = (const float*)d_in[8];
    const float* wo  = (const float*)d_in[9];
    const float* bo  = (const float*)d_in[10];
    float* out = (float*)d_out;

    cudaFuncSetAttribute(tg_av, cudaFuncAttributeMaxDynamicSharedMemorySize, AV_SMEM);

    gnx_kernel<<<BATCH * NG, 256>>>(x, gnw, gnb);

    wconv_kernel<<<4 * CH * CH / 256, 256>>>(wq, wk, wv, wo);

    dim3 gqk(CH / 128, HW / 128, BATCH * 2);
    tg_qk<<<gqk, THREADS, SM_BYTES>>>(bq, bk);

    dim3 gv(HW / 128, CH / 128, BATCH);
    tg_v<<<gv, THREADS, SM_BYTES>>>(bv);

    dim3 gs(HW / 128, HW / 128, BATCH);
    tg_score<<<gs, THREADS, SM_BYTES>>>();

    softmax_kernel<<<BATCH * HW, 256>>>();

    dim3 ga(CH / 128, HW / 128, BATCH);
    tg_av<<<ga, THREADS, AV_SMEM>>>();

    dim3 go(HW / 128, CH / 128, BATCH);
    tg_out<<<go, THREADS, SM_BYTES>>>(bo, x, out);
}

// round 14
// speedup vs baseline: 1.0424x; 1.0424x over previous
#include <cuda_runtime.h>
#include <cuda_fp16.h>
#include <cstdint>
#include <math.h>

#define BATCH 4
#define CH    512
#define HW    4096
#define NG    32

static const size_t SFE = (size_t)CH * HW;

// ================= scratch (device globals) =================
__device__ __half g_xnT[(size_t)BATCH * HW * CH];   // (i,c) fp16
__device__ __half g_q16[(size_t)BATCH * HW * CH];   // (i,c)
__device__ __half g_k16[(size_t)BATCH * HW * CH];   // (i,c)
__device__ __half g_v16[(size_t)BATCH * CH * HW];   // (c,i)
__device__ __half g_s16[(size_t)BATCH * HW * HW];   // scores fp16
__device__ __half g_P16[(size_t)BATCH * HW * HW];   // probs fp16
__device__ __half g_ot [(size_t)BATCH * HW * CH];   // (i,c)
__device__ __half g_w16[(size_t)4 * CH * CH];       // q,k,v,o weights

// ================= helpers =================
__device__ __forceinline__ uint32_t smem_u32(const void* p) {
    uint32_t a;
    asm("{ .reg .u64 t; cvta.to.shared.u64 t, %1; cvt.u32.u64 %0, t; }"
        : "=r"(a) : "l"(p));
    return a;
}
__device__ __forceinline__ uint32_t pack2h(__half a, __half b) {
    return (uint32_t)__half_as_ushort(a) |
           ((uint32_t)__half_as_ushort(b) << 16);
}

#define LDSM4(R, a) \
    asm volatile("ldmatrix.sync.aligned.m8n8.x4.shared.b16 {%0,%1,%2,%3}, [%4];" \
        : "=r"((R)[0]), "=r"((R)[1]), "=r"((R)[2]), "=r"((R)[3]) : "r"(a))

__device__ __forceinline__ void mma_h(float* d, const uint32_t* a,
                                      const uint32_t* b) {
    asm volatile(
        "mma.sync.aligned.m16n8k16.row.col.f32.f16.f16.f32 "
        "{%0,%1,%2,%3}, {%4,%5,%6,%7}, {%8,%9}, {%0,%1,%2,%3};"
        : "+f"(d[0]), "+f"(d[1]), "+f"(d[2]), "+f"(d[3])
        : "r"(a[0]), "r"(a[1]), "r"(a[2]), "r"(a[3]), "r"(b[0]), "r"(b[1]));
}

// smem: 2 matrices (A, B) of 128 rows x 32 halves padded to 80B rows; 2 stages.
#define ROWB   80
#define MATB   10240
#define STAGEB (2 * MATB)
#define SM_BYTES (2 * STAGEB)
#define THREADS 512

// ============================================================
// fp16 GEMM (fp32 accum) via mma.sync + ldmatrix. 16 warps, 32x32 warp tile.
// OUTM: 0 = fp32 [+bias/res], 2 = fp16.
// Ctile(128x128) = A(MxK) . B(NxK)^T ; K-major fp16; K % 32 == 0.
// ============================================================
template<int OUTM, bool BROW, bool BCOL, bool RES>
__device__ __forceinline__ void tgemm(
    const __half* __restrict__ A, int lda,
    const __half* __restrict__ B, int ldb,
    int K, float alpha,
    const float* __restrict__ bias_row, const float* __restrict__ bias_col,
    const float* __restrict__ res, int ldr,
    float* __restrict__ Cf, __half* __restrict__ Ch, int ldc)
{
    extern __shared__ char smem[];
    const uint32_t sb = smem_u32(smem);
    const int tid  = threadIdx.x;
    const int wid  = tid >> 5, lane = tid & 31;
    const int mw   = wid >> 2, nw = wid & 3;
    const int m0   = blockIdx.y * 128, n0 = blockIdx.x * 128;
    const int C    = K >> 5;

    float acc[2][4][4];
    #pragma unroll
    for (int i = 0; i < 2; i++)
        #pragma unroll
        for (int j = 0; j < 4; j++)
            #pragma unroll
            for (int q = 0; q < 4; q++) acc[i][j][q] = 0.f;

    auto load_chunk = [&](int ck) {
        const uint32_t stage = sb + (ck & 1) * STAGEB;
        #pragma unroll
        for (int i = 0; i < 2; i++) {
            const int unit = tid + THREADS * i;
            const int mat = unit >> 9;
            const int row = (unit >> 2) & 127;
            const int u   = unit & 3;
            const __half* src = (mat == 0) ? A : B;
            const int ld_ = (mat == 0) ? lda : ldb;
            const int r0  = (mat == 0) ? m0  : n0;
            const char* gsrc =
                (const char*)(src + (size_t)(r0 + row) * ld_ + ck * 32) + u * 16;
            const uint32_t dst = stage + mat * MATB + row * ROWB + u * 16;
            asm volatile("cp.async.cg.shared.global [%0], [%1], 16;"
                         :: "r"(dst), "l"(gsrc));
        }
        asm volatile("cp.async.commit_group;" ::: "memory");
    };

    load_chunk(0);

    const int gq = lane >> 2, qt = lane & 3;
    const int lnA_row = lane & 15;
    const int lnA_off = (lane >> 4) << 4;
    const int lnB_row = (lane & 7) + ((lane & 16) >> 1);
    const int lnB_off = (lane & 8) << 1;

    for (int c = 0; c < C; c++) {
        if (c + 1 < C) load_chunk(c + 1);
        if (c + 1 < C) asm volatile("cp.async.wait_group 1;" ::: "memory");
        else           asm volatile("cp.async.wait_group 0;" ::: "memory");
        __syncthreads();

        const uint32_t stage = sb + (c & 1) * STAGEB;

        #pragma unroll
        for (int ks = 0; ks < 2; ks++) {
            const uint32_t ko = ks * 32;
            uint32_t ah[2][4];
            #pragma unroll
            for (int mt = 0; mt < 2; mt++) {
                const uint32_t aAddr = stage +
                    (mw * 32 + mt * 16 + lnA_row) * ROWB + ko + lnA_off;
                LDSM4(ah[mt], aAddr);
            }
            #pragma unroll
            for (int p = 0; p < 2; p++) {
                const uint32_t bAddr = stage + MATB +
                    (nw * 32 + p * 16 + lnB_row) * ROWB + ko + lnB_off;
                uint32_t bh[4];
                LDSM4(bh, bAddr);
                #pragma unroll
                for (int half_ = 0; half_ < 2; half_++) {
                    const int nt = p * 2 + half_;
                    #pragma unroll
                    for (int mt = 0; mt < 2; mt++)
                        mma_h(acc[mt][nt], ah[mt], bh + half_ * 2);
                }
            }
        }
        __syncthreads();
    }

    #pragma unroll
    for (int mt = 0; mt < 2; mt++) {
        const int mA = m0 + mw * 32 + mt * 16 + gq;
        #pragma unroll
        for (int half_ = 0; half_ < 2; half_++) {
            const int m = mA + half_ * 8;
            const float br = BROW ? bias_row[m] : 0.f;
            #pragma unroll
            for (int nt = 0; nt < 4; nt++) {
                const int n = n0 + nw * 32 + nt * 8 + qt * 2;
                float vx = acc[mt][nt][half_ * 2 + 0] * alpha + br;
                float vy = acc[mt][nt][half_ * 2 + 1] * alpha + br;
                if (BCOL) { vx += bias_col[n]; vy += bias_col[n + 1]; }
                if (RES) {
                    const float* rp = res + (size_t)m * ldr + n;
                    vx += rp[0]; vy += rp[1];
                }
                if (OUTM == 0) {
                    float2 o = {vx, vy};
                    *(float2*)(Cf + (size_t)m * ldc + n) = o;
                } else {
                    *(uint32_t*)(Ch + (size_t)m * ldc + n) =
                        pack2h(__float2half(vx), __float2half(vy));
                }
            }
        }
    }
}

// ================= wrapper kernels =================

__global__ __launch_bounds__(THREADS, 1) void tg_qk(
    const float* __restrict__ bq, const float* __restrict__ bk)
{
    const int b = blockIdx.z >> 1, s = blockIdx.z & 1;
    __half* Cq = (s == 0 ? g_q16 : g_k16) + (size_t)b * HW * CH;
    tgemm<2, false, true, false>(
        g_xnT + (size_t)b * HW * CH, CH,
        g_w16 + (size_t)s * CH * CH, CH,
        CH, 1.f, nullptr, (s == 0 ? bq : bk), nullptr, 0,
        nullptr, Cq, CH);
}

__global__ __launch_bounds__(THREADS, 1) void tg_v(const float* __restrict__ bv)
{
    const int b = blockIdx.z;
    tgemm<2, true, false, false>(
        g_w16 + (size_t)2 * CH * CH, CH,
        g_xnT + (size_t)b * HW * CH, CH,
        CH, 1.f, bv, nullptr, nullptr, 0,
        nullptr, g_v16 + (size_t)b * CH * HW, HW);
}

__global__ __launch_bounds__(THREADS, 1) void tg_score()
{
    const int b = blockIdx.z;
    tgemm<2, false, false, false>(
        g_q16 + (size_t)b * HW * CH, CH,
        g_k16 + (size_t)b * HW * CH, CH,
        CH, 0.044194173824159216f, nullptr, nullptr, nullptr, 0,
        nullptr, g_s16 + (size_t)b * HW * HW, HW);
}

// Ot = P16 . v16^T -> fp16 (i,c)   (fp32 accumulate, plain tgemm)
__global__ __launch_bounds__(THREADS, 1) void tg_av()
{
    const int b = blockIdx.z;
    tgemm<2, false, false, false>(
        g_P16 + (size_t)b * HW * HW, HW,
        g_v16 + (size_t)b * CH * HW, HW,
        HW, 1.f, nullptr, nullptr, nullptr, 0,
        nullptr, g_ot + (size_t)b * HW * CH, CH);
}

// out = Wo . Ot^T + bo + x  (fp32 out + residual)
__global__ __launch_bounds__(THREADS, 1) void tg_out(
    const float* __restrict__ bo, const float* __restrict__ x,
    float* __restrict__ out)
{
    const int b = blockIdx.z;
    tgemm<0, true, false, true>(
        g_w16 + (size_t)3 * CH * CH, CH,
        g_ot + (size_t)b * HW * CH, CH,
        CH, 1.f, bo, nullptr, x + (size_t)b * SFE, HW,
        out + (size_t)b * SFE, nullptr, HW);
}

// ================= fused GroupNorm + transpose + fp16 =================
// One block per (batch, group): 16 ch x 4096. Writes g_xnT (i,c) fp16 directly.
__global__ __launch_bounds__(256) void gnx_kernel(
    const float* __restrict__ x, const float* __restrict__ gamma,
    const float* __restrict__ beta)
{
    const int bg = blockIdx.x;                 // b*32 + g
    const int b = bg >> 5, g = bg & 31;
    const size_t base = (size_t)bg * 16 * HW;
    const int n = 16 * HW;                     // 65536
    const int t = threadIdx.x;

    // ---- pass 1: stats ----
    const float4* xv = (const float4*)(x + base);
    float s = 0.f, ss = 0.f;
    for (int i = t; i < n / 4; i += 256) {
        float4 v = xv[i];
        s  += v.x + v.y + v.z + v.w;
        ss += v.x*v.x + v.y*v.y + v.z*v.z + v.w*v.w;
    }
    __shared__ float sh[64];
    #pragma unroll
    for (int o = 16; o > 0; o >>= 1) {
        s  += __shfl_xor_sync(~0u, s, o);
        ss += __shfl_xor_sync(~0u, ss, o);
    }
    const int warp = t >> 5, lane = t & 31;
    if (lane == 0) { sh[warp] = s; sh[32 + warp] = ss; }
    __syncthreads();
    if (warp == 0) {
        float a = (lane < 8) ? sh[lane] : 0.f;
        float bb = (lane < 8) ? sh[32 + lane] : 0.f;
        #pragma unroll
        for (int o = 4; o > 0; o >>= 1) {
            a  += __shfl_xor_sync(~0u, a, o);
            bb += __shfl_xor_sync(~0u, bb, o);
        }
        if (lane == 0) { sh[0] = a; sh[1] = bb; }
    }
    __syncthreads();
    const float mean = sh[0] / n;
    const float var  = sh[1] / n - mean * mean;
    const float inv  = rsqrtf(var + 1e-6f);
    const int gbase = g * 16;

    // ---- pass 2: normalize + transpose to (i,c) fp16 ----
    const int tc8 = (t >> 7) * 8;              // 0 or 8
    const int ti  = t & 127;
    float ga[8], be[8];
    #pragma unroll
    for (int q = 0; q < 8; q++) {
        ga[q] = gamma[gbase + tc8 + q] * inv;
        be[q] = beta[gbase + tc8 + q];
    }
    __shared__ float ts[16][129];
    for (int tile = 0; tile < 32; tile++) {
        const int i0 = tile * 128;
        #pragma unroll
        for (int j = 0; j < 8; j++) {
            const int idx = t + 256 * j;       // 0..2047
            const int c = idx >> 7, i = idx & 127;
            ts[c][i] = x[base + (size_t)c * HW + i0 + i];
        }
        __syncthreads();
        uint4 hv;
        uint32_t* hw_ = (uint32_t*)&hv;
        #pragma unroll
        for (int q2 = 0; q2 < 4; q2++) {
            const float v0 = (ts[tc8 + q2*2    ][ti] - mean) * ga[q2*2]     + be[q2*2];
            const float v1 = (ts[tc8 + q2*2 + 1][ti] - mean) * ga[q2*2 + 1] + be[q2*2 + 1];
            hw_[q2] = pack2h(__float2half(v0), __float2half(v1));
        }
        *(uint4*)(g_xnT + ((size_t)b * HW + i0 + ti) * CH + gbase + tc8) = hv;
        __syncthreads();
    }
}

// ================= weight convert =================
__global__ __launch_bounds__(256) void wconv_kernel(
    const float* __restrict__ wq, const float* __restrict__ wk,
    const float* __restrict__ wv, const float* __restrict__ wo)
{
    const size_t idx = (size_t)blockIdx.x * 256 + threadIdx.x;
    const int which = (int)(idx >> 18);
    const size_t off = idx & ((1 << 18) - 1);
    const float* w = (which == 0) ? wq : (which == 1) ? wk : (which == 2) ? wv : wo;
    g_w16[idx] = __float2half(w[off]);
}

// ================= softmax: fp16 in -> fp16 out =================
__global__ __launch_bounds__(256) void softmax_kernel()
{
    const size_t row = blockIdx.x;
    const uint2* pv = (const uint2*)(g_s16 + row * HW);
    __half* ph = g_P16 + row * HW;
    const int t = threadIdx.x;
    float v[4][4];
    float mx = -1e30f;
    #pragma unroll
    for (int j = 0; j < 4; j++) {
        uint2 u = pv[t + 256 * j];
        __half2 a = *(__half2*)&u.x, b = *(__half2*)&u.y;
        float2 fa = __half22float2(a), fb = __half22float2(b);
        v[j][0] = fa.x; v[j][1] = fa.y; v[j][2] = fb.x; v[j][3] = fb.y;
        mx = fmaxf(mx, fmaxf(fmaxf(v[j][0], v[j][1]), fmaxf(v[j][2], v[j][3])));
    }
    __shared__ float sh[8];
    #pragma unroll
    for (int o = 16; o > 0; o >>= 1) mx = fmaxf(mx, __shfl_xor_sync(~0u, mx, o));
    if ((t & 31) == 0) sh[t >> 5] = mx;
    __syncthreads();
    const float m0 = fmaxf(fmaxf(fmaxf(sh[0], sh[1]), fmaxf(sh[2], sh[3])),
                           fmaxf(fmaxf(sh[4], sh[5]), fmaxf(sh[6], sh[7])));
    __syncthreads();
    float sum = 0.f;
    #pragma unroll
    for (int j = 0; j < 4; j++) {
        #pragma unroll
        for (int q = 0; q < 4; q++) {
            v[j][q] = __expf(v[j][q] - m0);
            sum += v[j][q];
        }
    }
    #pragma unroll
    for (int o = 16; o > 0; o >>= 1) sum += __shfl_xor_sync(~0u, sum, o);
    if ((t & 31) == 0) sh[t >> 5] = sum;
    __syncthreads();
    const float tot = sh[0]+sh[1]+sh[2]+sh[3]+sh[4]+sh[5]+sh[6]+sh[7];
    const float inv = 1.f / tot;
    #pragma unroll
    for (int j = 0; j < 4; j++) {
        const int eo = (t + 256 * j) * 4;
        uint2 hv = { pack2h(__float2half(v[j][0] * inv), __float2half(v[j][1] * inv)),
                     pack2h(__float2half(v[j][2] * inv), __float2half(v[j][3] * inv)) };
        *(uint2*)(ph + eo) = hv;
    }
}

// ============================================================
extern "C" void kernel_launch(void* const* d_in, const int* in_sizes, int n_in,
                              void* d_out, int out_size)
{
    const float* x   = (const float*)d_in[0];
    const float* gnw = (const float*)d_in[1];
    const float* gnb = (const float*)d_in[2];
    const float* wq  = (const float*)d_in[3];
    const float* bq  = (const float*)d_in[4];
    const float* wk  = (const float*)d_in[5];
    const float* bk  = (const float*)d_in[6];
    const float* wv  = (const float*)d_in[7];
    const float* bv  = (const float*)d_in[8];
    const float* wo  = (const float*)d_in[9];
    const float* bo  = (const float*)d_in[10];
    float* out = (float*)d_out;

    gnx_kernel<<<BATCH * NG, 256>>>(x, gnw, gnb);

    wconv_kernel<<<4 * CH * CH / 256, 256>>>(wq, wk, wv, wo);

    dim3 gqk(CH / 128, HW / 128, BATCH * 2);
    tg_qk<<<gqk, THREADS, SM_BYTES>>>(bq, bk);

    dim3 gv(HW / 128, CH / 128, BATCH);
    tg_v<<<gv, THREADS, SM_BYTES>>>(bv);

    dim3 gs(HW / 128, HW / 128, BATCH);
    tg_score<<<gs, THREADS, SM_BYTES>>>();

    softmax_kernel<<<BATCH * HW, 256>>>();

    dim3 ga(CH / 128, HW / 128, BATCH);
    tg_av<<<ga, THREADS, SM_BYTES>>>();

    dim3 go(HW / 128, CH / 128, BATCH);
    tg_out<<<go, THREADS, SM_BYTES>>>(bo, x, out);
}

// round 15
// speedup vs baseline: 1.2241x; 1.1743x over previous
#include <cuda_runtime.h>
#include <cuda_fp16.h>
#include <cstdint>
#include <math.h>

#define BATCH 4
#define CH    512
#define HW    4096
#define NG    32

static const size_t SFE = (size_t)CH * HW;

// ================= scratch (device globals) =================
__device__ __half g_xnT[(size_t)BATCH * HW * CH];   // (i,c) fp16
__device__ __half g_q16[(size_t)BATCH * HW * CH];   // (i,c)
__device__ __half g_k16[(size_t)BATCH * HW * CH];   // (i,c)
__device__ __half g_v16[(size_t)BATCH * CH * HW];   // (c,i)
__device__ __half g_s16[(size_t)BATCH * HW * HW];   // scores fp16
__device__ __half g_P16[(size_t)BATCH * HW * HW];   // probs fp16
__device__ __half g_ot [(size_t)BATCH * HW * CH];   // (i,c)
__device__ __half g_w16[(size_t)4 * CH * CH];       // q,k,v,o weights

// ================= helpers =================
__device__ __forceinline__ uint32_t smem_u32(const void* p) {
    uint32_t a;
    asm("{ .reg .u64 t; cvta.to.shared.u64 t, %1; cvt.u32.u64 %0, t; }"
        : "=r"(a) : "l"(p));
    return a;
}
__device__ __forceinline__ uint32_t pack2h(__half a, __half b) {
    return (uint32_t)__half_as_ushort(a) |
           ((uint32_t)__half_as_ushort(b) << 16);
}

#define LDSM4(R, a) \
    asm volatile("ldmatrix.sync.aligned.m8n8.x4.shared.b16 {%0,%1,%2,%3}, [%4];" \
        : "=r"((R)[0]), "=r"((R)[1]), "=r"((R)[2]), "=r"((R)[3]) : "r"(a))

__device__ __forceinline__ void mma_h(float* d, const uint32_t* a,
                                      const uint32_t* b) {
    asm volatile(
        "mma.sync.aligned.m16n8k16.row.col.f32.f16.f16.f32 "
        "{%0,%1,%2,%3}, {%4,%5,%6,%7}, {%8,%9}, {%0,%1,%2,%3};"
        : "+f"(d[0]), "+f"(d[1]), "+f"(d[2]), "+f"(d[3])
        : "r"(a[0]), "r"(a[1]), "r"(a[2]), "r"(a[3]), "r"(b[0]), "r"(b[1]));
}

// smem: 2 matrices (A, B) of 128 rows x 64 halves (128B) padded to 144B rows.
// 3 stages, ONE __syncthreads per 64-K chunk.
#define ROWB   144
#define MATB   (128 * ROWB)      // 18432
#define STAGEB (2 * MATB)        // 36864
#define SM_BYTES (3 * STAGEB)    // 110592
#define THREADS 512

// ============================================================
// fp16 GEMM (fp32 accum) via mma.sync + ldmatrix. 16 warps, 32x32 warp tile.
// OUTM: 0 = fp32 [+bias/res], 2 = fp16.
// Ctile(128x128) = A(MxK) . B(NxK)^T ; K-major fp16; K % 64 == 0.
// ============================================================
template<int OUTM, bool BROW, bool BCOL, bool RES>
__device__ __forceinline__ void tgemm(
    const __half* __restrict__ A, int lda,
    const __half* __restrict__ B, int ldb,
    int K, float alpha,
    const float* __restrict__ bias_row, const float* __restrict__ bias_col,
    const float* __restrict__ res, int ldr,
    float* __restrict__ Cf, __half* __restrict__ Ch, int ldc)
{
    extern __shared__ char smem[];
    const uint32_t sb = smem_u32(smem);
    const int tid  = threadIdx.x;
    const int wid  = tid >> 5, lane = tid & 31;
    const int mw   = wid >> 2, nw = wid & 3;
    const int m0   = blockIdx.y * 128, n0 = blockIdx.x * 128;
    const int C    = K >> 6;                  // 64-wide k chunks

    float acc[2][4][4];
    #pragma unroll
    for (int i = 0; i < 2; i++)
        #pragma unroll
        for (int j = 0; j < 4; j++)
            #pragma unroll
            for (int q = 0; q < 4; q++) acc[i][j][q] = 0.f;

    // issue one 64-K chunk (2 mats x 128 rows x 128B = 2048 x 16B units)
    auto load_chunk = [&](int ck, int sidx) {
        const uint32_t stage = sb + sidx * STAGEB;
        #pragma unroll
        for (int i = 0; i < 4; i++) {
            const int unit = tid + THREADS * i;
            const int mat = unit >> 10;
            const int row = (unit >> 3) & 127;
            const int u   = unit & 7;
            const __half* src = (mat == 0) ? A : B;
            const int ld_ = (mat == 0) ? lda : ldb;
            const int r0  = (mat == 0) ? m0  : n0;
            const char* gsrc =
                (const char*)(src + (size_t)(r0 + row) * ld_ + ck * 64) + u * 16;
            const uint32_t dst = stage + mat * MATB + row * ROWB + u * 16;
            asm volatile("cp.async.cg.shared.global [%0], [%1], 16;"
                         :: "r"(dst), "l"(gsrc));
        }
        asm volatile("cp.async.commit_group;" ::: "memory");
    };

    load_chunk(0, 0);
    if (C > 1) load_chunk(1, 1);

    const int gq = lane >> 2, qt = lane & 3;
    const int lnA_row = lane & 15;
    const int lnA_off = (lane >> 4) << 4;
    const int lnB_row = (lane & 7) + ((lane & 16) >> 1);
    const int lnB_off = (lane & 8) << 1;

    int s_cur = 0, s_nxt = (C > 2) ? 2 : 0;   // stage of chunk c, stage for c+2
    for (int c = 0; c < C; c++) {
        if (c + 1 < C) asm volatile("cp.async.wait_group 1;" ::: "memory");
        else           asm volatile("cp.async.wait_group 0;" ::: "memory");
        __syncthreads();
        // barrier above guarantees iter c-1 readers of stage s_nxt are done
        if (c + 2 < C) {
            load_chunk(c + 2, s_nxt);
            if (++s_nxt == 3) s_nxt = 0;
        }

        const uint32_t stage = sb + s_cur * STAGEB;
        if (++s_cur == 3) s_cur = 0;

        #pragma unroll
        for (int ks = 0; ks < 4; ks++) {
            const uint32_t ko = ks * 32;
            uint32_t ah[2][4];
            #pragma unroll
            for (int mt = 0; mt < 2; mt++) {
                const uint32_t aAddr = stage +
                    (mw * 32 + mt * 16 + lnA_row) * ROWB + ko + lnA_off;
                LDSM4(ah[mt], aAddr);
            }
            #pragma unroll
            for (int p = 0; p < 2; p++) {
                const uint32_t bAddr = stage + MATB +
                    (nw * 32 + p * 16 + lnB_row) * ROWB + ko + lnB_off;
                uint32_t bh[4];
                LDSM4(bh, bAddr);
                #pragma unroll
                for (int half_ = 0; half_ < 2; half_++) {
                    const int nt = p * 2 + half_;
                    #pragma unroll
                    for (int mt = 0; mt < 2; mt++)
                        mma_h(acc[mt][nt], ah[mt], bh + half_ * 2);
                }
            }
        }
        // NO trailing __syncthreads: next iter's barrier (before any smem
        // overwrite is issued) provides the ordering.
    }
    __syncthreads();

    #pragma unroll
    for (int mt = 0; mt < 2; mt++) {
        const int mA = m0 + mw * 32 + mt * 16 + gq;
        #pragma unroll
        for (int half_ = 0; half_ < 2; half_++) {
            const int m = mA + half_ * 8;
            const float br = BROW ? bias_row[m] : 0.f;
            #pragma unroll
            for (int nt = 0; nt < 4; nt++) {
                const int n = n0 + nw * 32 + nt * 8 + qt * 2;
                float vx = acc[mt][nt][half_ * 2 + 0] * alpha + br;
                float vy = acc[mt][nt][half_ * 2 + 1] * alpha + br;
                if (BCOL) { vx += bias_col[n]; vy += bias_col[n + 1]; }
                if (RES) {
                    const float* rp = res + (size_t)m * ldr + n;
                    vx += rp[0]; vy += rp[1];
                }
                if (OUTM == 0) {
                    float2 o = {vx, vy};
                    *(float2*)(Cf + (size_t)m * ldc + n) = o;
                } else {
                    *(uint32_t*)(Ch + (size_t)m * ldc + n) =
                        pack2h(__float2half(vx), __float2half(vy));
                }
            }
        }
    }
}

// ================= wrapper kernels =================

__global__ __launch_bounds__(THREADS, 1) void tg_qk(
    const float* __restrict__ bq, const float* __restrict__ bk)
{
    const int b = blockIdx.z >> 1, s = blockIdx.z & 1;
    __half* Cq = (s == 0 ? g_q16 : g_k16) + (size_t)b * HW * CH;
    tgemm<2, false, true, false>(
        g_xnT + (size_t)b * HW * CH, CH,
        g_w16 + (size_t)s * CH * CH, CH,
        CH, 1.f, nullptr, (s == 0 ? bq : bk), nullptr, 0,
        nullptr, Cq, CH);
}

__global__ __launch_bounds__(THREADS, 1) void tg_v(const float* __restrict__ bv)
{
    const int b = blockIdx.z;
    tgemm<2, true, false, false>(
        g_w16 + (size_t)2 * CH * CH, CH,
        g_xnT + (size_t)b * HW * CH, CH,
        CH, 1.f, bv, nullptr, nullptr, 0,
        nullptr, g_v16 + (size_t)b * CH * HW, HW);
}

__global__ __launch_bounds__(THREADS, 1) void tg_score()
{
    const int b = blockIdx.z;
    tgemm<2, false, false, false>(
        g_q16 + (size_t)b * HW * CH, CH,
        g_k16 + (size_t)b * HW * CH, CH,
        CH, 0.044194173824159216f, nullptr, nullptr, nullptr, 0,
        nullptr, g_s16 + (size_t)b * HW * HW, HW);
}

// Ot = P16 . v16^T -> fp16 (i,c)
__global__ __launch_bounds__(THREADS, 1) void tg_av()
{
    const int b = blockIdx.z;
    tgemm<2, false, false, false>(
        g_P16 + (size_t)b * HW * HW, HW,
        g_v16 + (size_t)b * CH * HW, HW,
        HW, 1.f, nullptr, nullptr, nullptr, 0,
        nullptr, g_ot + (size_t)b * HW * CH, CH);
}

// out = Wo . Ot^T + bo + x  (fp32 out + residual)
__global__ __launch_bounds__(THREADS, 1) void tg_out(
    const float* __restrict__ bo, const float* __restrict__ x,
    float* __restrict__ out)
{
    const int b = blockIdx.z;
    tgemm<0, true, false, true>(
        g_w16 + (size_t)3 * CH * CH, CH,
        g_ot + (size_t)b * HW * CH, CH,
        CH, 1.f, bo, nullptr, x + (size_t)b * SFE, HW,
        out + (size_t)b * SFE, nullptr, HW);
}

// ================= fused GroupNorm + transpose + fp16 =================
__global__ __launch_bounds__(256) void gnx_kernel(
    const float* __restrict__ x, const float* __restrict__ gamma,
    const float* __restrict__ beta)
{
    const int bg = blockIdx.x;                 // b*32 + g
    const int b = bg >> 5, g = bg & 31;
    const size_t base = (size_t)bg * 16 * HW;
    const int n = 16 * HW;
    const int t = threadIdx.x;

    const float4* xv = (const float4*)(x + base);
    float s = 0.f, ss = 0.f;
    for (int i = t; i < n / 4; i += 256) {
        float4 v = xv[i];
        s  += v.x + v.y + v.z + v.w;
        ss += v.x*v.x + v.y*v.y + v.z*v.z + v.w*v.w;
    }
    __shared__ float sh[64];
    #pragma unroll
    for (int o = 16; o > 0; o >>= 1) {
        s  += __shfl_xor_sync(~0u, s, o);
        ss += __shfl_xor_sync(~0u, ss, o);
    }
    const int warp = t >> 5, lane = t & 31;
    if (lane == 0) { sh[warp] = s; sh[32 + warp] = ss; }
    __syncthreads();
    if (warp == 0) {
        float a = (lane < 8) ? sh[lane] : 0.f;
        float bb = (lane < 8) ? sh[32 + lane] : 0.f;
        #pragma unroll
        for (int o = 4; o > 0; o >>= 1) {
            a  += __shfl_xor_sync(~0u, a, o);
            bb += __shfl_xor_sync(~0u, bb, o);
        }
        if (lane == 0) { sh[0] = a; sh[1] = bb; }
    }
    __syncthreads();
    const float mean = sh[0] / n;
    const float var  = sh[1] / n - mean * mean;
    const float inv  = rsqrtf(var + 1e-6f);
    const int gbase = g * 16;

    const int tc8 = (t >> 7) * 8;
    const int ti  = t & 127;
    float ga[8], be[8];
    #pragma unroll
    for (int q = 0; q < 8; q++) {
        ga[q] = gamma[gbase + tc8 + q] * inv;
        be[q] = beta[gbase + tc8 + q];
    }
    __shared__ float ts[16][129];
    for (int tile = 0; tile < 32; tile++) {
        const int i0 = tile * 128;
        #pragma unroll
        for (int j = 0; j < 8; j++) {
            const int idx = t + 256 * j;
            const int c = idx >> 7, i = idx & 127;
            ts[c][i] = x[base + (size_t)c * HW + i0 + i];
        }
        __syncthreads();
        uint4 hv;
        uint32_t* hw_ = (uint32_t*)&hv;
        #pragma unroll
        for (int q2 = 0; q2 < 4; q2++) {
            const float v0 = (ts[tc8 + q2*2    ][ti] - mean) * ga[q2*2]     + be[q2*2];
            const float v1 = (ts[tc8 + q2*2 + 1][ti] - mean) * ga[q2*2 + 1] + be[q2*2 + 1];
            hw_[q2] = pack2h(__float2half(v0), __float2half(v1));
        }
        *(uint4*)(g_xnT + ((size_t)b * HW + i0 + ti) * CH + gbase + tc8) = hv;
        __syncthreads();
    }
}

// ================= weight convert =================
__global__ __launch_bounds__(256) void wconv_kernel(
    const float* __restrict__ wq, const float* __restrict__ wk,
    const float* __restrict__ wv, const float* __restrict__ wo)
{
    const size_t idx = (size_t)blockIdx.x * 256 + threadIdx.x;
    const int which = (int)(idx >> 18);
    const size_t off = idx & ((1 << 18) - 1);
    const float* w = (which == 0) ? wq : (which == 1) ? wk : (which == 2) ? wv : wo;
    g_w16[idx] = __float2half(w[off]);
}

// ================= softmax: fp16 in -> fp16 out =================
__global__ __launch_bounds__(256) void softmax_kernel()
{
    const size_t row = blockIdx.x;
    const uint2* pv = (const uint2*)(g_s16 + row * HW);
    __half* ph = g_P16 + row * HW;
    const int t = threadIdx.x;
    float v[4][4];
    float mx = -1e30f;
    #pragma unroll
    for (int j = 0; j < 4; j++) {
        uint2 u = pv[t + 256 * j];
        __half2 a = *(__half2*)&u.x, b = *(__half2*)&u.y;
        float2 fa = __half22float2(a), fb = __half22float2(b);
        v[j][0] = fa.x; v[j][1] = fa.y; v[j][2] = fb.x; v[j][3] = fb.y;
        mx = fmaxf(mx, fmaxf(fmaxf(v[j][0], v[j][1]), fmaxf(v[j][2], v[j][3])));
    }
    __shared__ float sh[8];
    #pragma unroll
    for (int o = 16; o > 0; o >>= 1) mx = fmaxf(mx, __shfl_xor_sync(~0u, mx, o));
    if ((t & 31) == 0) sh[t >> 5] = mx;
    __syncthreads();
    const float m0 = fmaxf(fmaxf(fmaxf(sh[0], sh[1]), fmaxf(sh[2], sh[3])),
                           fmaxf(fmaxf(sh[4], sh[5]), fmaxf(sh[6], sh[7])));
    __syncthreads();
    float sum = 0.f;
    #pragma unroll
    for (int j = 0; j < 4; j++) {
        #pragma unroll
        for (int q = 0; q < 4; q++) {
            v[j][q] = __expf(v[j][q] - m0);
            sum += v[j][q];
        }
    }
    #pragma unroll
    for (int o = 16; o > 0; o >>= 1) sum += __shfl_xor_sync(~0u, sum, o);
    if ((t & 31) == 0) sh[t >> 5] = sum;
    __syncthreads();
    const float tot = sh[0]+sh[1]+sh[2]+sh[3]+sh[4]+sh[5]+sh[6]+sh[7];
    const float inv = 1.f / tot;
    #pragma unroll
    for (int j = 0; j < 4; j++) {
        const int eo = (t + 256 * j) * 4;
        uint2 hv = { pack2h(__float2half(v[j][0] * inv), __float2half(v[j][1] * inv)),
                     pack2h(__float2half(v[j][2] * inv), __float2half(v[j][3] * inv)) };
        *(uint2*)(ph + eo) = hv;
    }
}

// ============================================================
extern "C" void kernel_launch(void* const* d_in, const int* in_sizes, int n_in,
                              void* d_out, int out_size)
{
    const float* x   = (const float*)d_in[0];
    const float* gnw = (const float*)d_in[1];
    const float* gnb = (const float*)d_in[2];
    const float* wq  = (const float*)d_in[3];
    const float* bq  = (const float*)d_in[4];
    const float* wk  = (const float*)d_in[5];
    const float* bk  = (const float*)d_in[6];
    const float* wv  = (const float*)d_in[7];
    const float* bv  = (const float*)d_in[8];
    const float* wo  = (const float*)d_in[9];
    const float* bo  = (const float*)d_in[10];
    float* out = (float*)d_out;

    cudaFuncSetAttribute(tg_qk,    cudaFuncAttributeMaxDynamicSharedMemorySize, SM_BYTES);
    cudaFuncSetAttribute(tg_v,     cudaFuncAttributeMaxDynamicSharedMemorySize, SM_BYTES);
    cudaFuncSetAttribute(tg_score, cudaFuncAttributeMaxDynamicSharedMemorySize, SM_BYTES);
    cudaFuncSetAttribute(tg_av,    cudaFuncAttributeMaxDynamicSharedMemorySize, SM_BYTES);
    cudaFuncSetAttribute(tg_out,   cudaFuncAttributeMaxDynamicSharedMemorySize, SM_BYTES);

    gnx_kernel<<<BATCH * NG, 256>>>(x, gnw, gnb);

    wconv_kernel<<<4 * CH * CH / 256, 256>>>(wq, wk, wv, wo);

    dim3 gqk(CH / 128, HW / 128, BATCH * 2);
    tg_qk<<<gqk, THREADS, SM_BYTES>>>(bq, bk);

    dim3 gv(HW / 128, CH / 128, BATCH);
    tg_v<<<gv, THREADS, SM_BYTES>>>(bv);

    dim3 gs(HW / 128, HW / 128, BATCH);
    tg_score<<<gs, THREADS, SM_BYTES>>>();

    softmax_kernel<<<BATCH * HW, 256>>>();

    dim3 ga(CH / 128, HW / 128, BATCH);
    tg_av<<<ga, THREADS, SM_BYTES>>>();

    dim3 go(HW / 128, CH / 128, BATCH);
    tg_out<<<go, THREADS, SM_BYTES>>>(bo, x, out);
}

// round 16
// speedup vs baseline: 1.3373x; 1.0925x over previous
#include <cuda_runtime.h>
#include <cuda_fp16.h>
#include <cstdint>
#include <math.h>

#define BATCH 4
#define CH    512
#define HW    4096
#define NG    32

static const size_t SFE = (size_t)CH * HW;

// ================= scratch (device globals) =================
__device__ __half g_xnT[(size_t)BATCH * HW * CH];   // (i,c) fp16
__device__ __half g_q16[(size_t)BATCH * HW * CH];   // (i,c)
__device__ __half g_k16[(size_t)BATCH * HW * CH];   // (i,c)
__device__ __half g_v16[(size_t)BATCH * CH * HW];   // (c,i)
__device__ __half g_s16[(size_t)BATCH * HW * HW];   // scores fp16
__device__ __half g_P16[(size_t)BATCH * HW * HW];   // probs fp16
__device__ __half g_ot [(size_t)BATCH * HW * CH];   // (i,c)
__device__ __half g_w16[(size_t)4 * CH * CH];       // q,k,v,o weights

// ================= helpers =================
__device__ __forceinline__ uint32_t smem_u32(const void* p) {
    uint32_t a;
    asm("{ .reg .u64 t; cvta.to.shared.u64 t, %1; cvt.u32.u64 %0, t; }"
        : "=r"(a) : "l"(p));
    return a;
}
__device__ __forceinline__ uint32_t pack2h(__half a, __half b) {
    return (uint32_t)__half_as_ushort(a) |
           ((uint32_t)__half_as_ushort(b) << 16);
}

#define LDSM4(R, a) \
    asm volatile("ldmatrix.sync.aligned.m8n8.x4.shared.b16 {%0,%1,%2,%3}, [%4];" \
        : "=r"((R)[0]), "=r"((R)[1]), "=r"((R)[2]), "=r"((R)[3]) : "r"(a))

__device__ __forceinline__ void mma_h(float* d, const uint32_t* a,
                                      const uint32_t* b) {
    asm volatile(
        "mma.sync.aligned.m16n8k16.row.col.f32.f16.f16.f32 "
        "{%0,%1,%2,%3}, {%4,%5,%6,%7}, {%8,%9}, {%0,%1,%2,%3};"
        : "+f"(d[0]), "+f"(d[1]), "+f"(d[2]), "+f"(d[3])
        : "r"(a[0]), "r"(a[1]), "r"(a[2]), "r"(a[3]), "r"(b[0]), "r"(b[1]));
}

// CTA tile 128m x 256n, warp tile 32m x 64n (4x4 warp grid, 16 warps).
// smem per stage: A 128 rows + B 256 rows, 64 halves (128B) padded to 144B.
// 3 stages, ONE __syncthreads per 64-K chunk.
#define ROWB   144
#define MATA   (128 * ROWB)          // 18432
#define MATBB  (256 * ROWB)          // 36864
#define STAGEB (MATA + MATBB)        // 55296
#define SM_BYTES (3 * STAGEB)        // 165888
#define THREADS 512

// ============================================================
// fp16 GEMM (fp32 accum) via mma.sync + ldmatrix.
// OUTM: 0 = fp32 [+bias/res], 2 = fp16.
// Ctile(128x256) = A(MxK) . B(NxK)^T ; K-major fp16; K % 64 == 0, N % 256 == 0.
// ============================================================
template<int OUTM, bool BROW, bool BCOL, bool RES>
__device__ __forceinline__ void tgemm(
    const __half* __restrict__ A, int lda,
    const __half* __restrict__ B, int ldb,
    int K, float alpha,
    const float* __restrict__ bias_row, const float* __restrict__ bias_col,
    const float* __restrict__ res, int ldr,
    float* __restrict__ Cf, __half* __restrict__ Ch, int ldc)
{
    extern __shared__ char smem[];
    const uint32_t sb = smem_u32(smem);
    const int tid  = threadIdx.x;
    const int wid  = tid >> 5, lane = tid & 31;
    const int mw   = wid >> 2, nw = wid & 3;
    const int m0   = blockIdx.y * 128, n0 = blockIdx.x * 256;
    const int C    = K >> 6;                  // 64-wide k chunks

    float acc[2][8][4];
    #pragma unroll
    for (int i = 0; i < 2; i++)
        #pragma unroll
        for (int j = 0; j < 8; j++)
            #pragma unroll
            for (int q = 0; q < 4; q++) acc[i][j][q] = 0.f;

    // one 64-K chunk: A 128 rows + B 256 rows, 128B each = 3072 x 16B units
    auto load_chunk = [&](int ck, int sidx) {
        const uint32_t stage = sb + sidx * STAGEB;
        #pragma unroll
        for (int i = 0; i < 6; i++) {
            const int unit = tid + THREADS * i;         // 0..3071
            const bool isA = unit < 1024;
            const int row = isA ? (unit >> 3) : ((unit - 1024) >> 3);
            const int u   = unit & 7;
            const __half* src = isA ? A : B;
            const int ld_ = isA ? lda : ldb;
            const int r0  = isA ? m0  : n0;
            const char* gsrc =
                (const char*)(src + (size_t)(r0 + row) * ld_ + ck * 64) + u * 16;
            const uint32_t dst = stage + (isA ? 0 : MATA) + row * ROWB + u * 16;
            asm volatile("cp.async.cg.shared.global [%0], [%1], 16;"
                         :: "r"(dst), "l"(gsrc));
        }
        asm volatile("cp.async.commit_group;" ::: "memory");
    };

    load_chunk(0, 0);
    if (C > 1) load_chunk(1, 1);

    const int gq = lane >> 2, qt = lane & 3;
    const int lnA_row = lane & 15;
    const int lnA_off = (lane >> 4) << 4;
    const int lnB_row = (lane & 7) + ((lane & 16) >> 1);
    const int lnB_off = (lane & 8) << 1;

    int s_cur = 0, s_nxt = (C > 2) ? 2 : 0;
    for (int c = 0; c < C; c++) {
        if (c + 1 < C) asm volatile("cp.async.wait_group 1;" ::: "memory");
        else           asm volatile("cp.async.wait_group 0;" ::: "memory");
        __syncthreads();
        if (c + 2 < C) {
            load_chunk(c + 2, s_nxt);
            if (++s_nxt == 3) s_nxt = 0;
        }

        const uint32_t stage = sb + s_cur * STAGEB;
        if (++s_cur == 3) s_cur = 0;

        #pragma unroll
        for (int ks = 0; ks < 4; ks++) {
            const uint32_t ko = ks * 32;
            uint32_t ah[2][4];
            #pragma unroll
            for (int mt = 0; mt < 2; mt++) {
                const uint32_t aAddr = stage +
                    (mw * 32 + mt * 16 + lnA_row) * ROWB + ko + lnA_off;
                LDSM4(ah[mt], aAddr);
            }
            #pragma unroll
            for (int p = 0; p < 4; p++) {
                const uint32_t bAddr = stage + MATA +
                    (nw * 64 + p * 16 + lnB_row) * ROWB + ko + lnB_off;
                uint32_t bh[4];
                LDSM4(bh, bAddr);
                #pragma unroll
                for (int half_ = 0; half_ < 2; half_++) {
                    const int nt = p * 2 + half_;
                    #pragma unroll
                    for (int mt = 0; mt < 2; mt++)
                        mma_h(acc[mt][nt], ah[mt], bh + half_ * 2);
                }
            }
        }
    }
    __syncthreads();

    #pragma unroll
    for (int mt = 0; mt < 2; mt++) {
        const int mA = m0 + mw * 32 + mt * 16 + gq;
        #pragma unroll
        for (int half_ = 0; half_ < 2; half_++) {
            const int m = mA + half_ * 8;
            const float br = BROW ? bias_row[m] : 0.f;
            #pragma unroll
            for (int nt = 0; nt < 8; nt++) {
                const int n = n0 + nw * 64 + nt * 8 + qt * 2;
                float vx = acc[mt][nt][half_ * 2 + 0] * alpha + br;
                float vy = acc[mt][nt][half_ * 2 + 1] * alpha + br;
                if (BCOL) { vx += bias_col[n]; vy += bias_col[n + 1]; }
                if (RES) {
                    const float* rp = res + (size_t)m * ldr + n;
                    vx += rp[0]; vy += rp[1];
                }
                if (OUTM == 0) {
                    float2 o = {vx, vy};
                    *(float2*)(Cf + (size_t)m * ldc + n) = o;
                } else {
                    *(uint32_t*)(Ch + (size_t)m * ldc + n) =
                        pack2h(__float2half(vx), __float2half(vy));
                }
            }
        }
    }
}

// ================= wrapper kernels =================

__global__ __launch_bounds__(THREADS, 1) void tg_qk(
    const float* __restrict__ bq, const float* __restrict__ bk)
{
    const int b = blockIdx.z >> 1, s = blockIdx.z & 1;
    __half* Cq = (s == 0 ? g_q16 : g_k16) + (size_t)b * HW * CH;
    tgemm<2, false, true, false>(
        g_xnT + (size_t)b * HW * CH, CH,
        g_w16 + (size_t)s * CH * CH, CH,
        CH, 1.f, nullptr, (s == 0 ? bq : bk), nullptr, 0,
        nullptr, Cq, CH);
}

__global__ __launch_bounds__(THREADS, 1) void tg_v(const float* __restrict__ bv)
{
    const int b = blockIdx.z;
    tgemm<2, true, false, false>(
        g_w16 + (size_t)2 * CH * CH, CH,
        g_xnT + (size_t)b * HW * CH, CH,
        CH, 1.f, bv, nullptr, nullptr, 0,
        nullptr, g_v16 + (size_t)b * CH * HW, HW);
}

__global__ __launch_bounds__(THREADS, 1) void tg_score()
{
    const int b = blockIdx.z;
    tgemm<2, false, false, false>(
        g_q16 + (size_t)b * HW * CH, CH,
        g_k16 + (size_t)b * HW * CH, CH,
        CH, 0.044194173824159216f, nullptr, nullptr, nullptr, 0,
        nullptr, g_s16 + (size_t)b * HW * HW, HW);
}

// Ot = P16 . v16^T -> fp16 (i,c)
__global__ __launch_bounds__(THREADS, 1) void tg_av()
{
    const int b = blockIdx.z;
    tgemm<2, false, false, false>(
        g_P16 + (size_t)b * HW * HW, HW,
        g_v16 + (size_t)b * CH * HW, HW,
        HW, 1.f, nullptr, nullptr, nullptr, 0,
        nullptr, g_ot + (size_t)b * HW * CH, CH);
}

// out = Wo . Ot^T + bo + x  (fp32 out + residual)
__global__ __launch_bounds__(THREADS, 1) void tg_out(
    const float* __restrict__ bo, const float* __restrict__ x,
    float* __restrict__ out)
{
    const int b = blockIdx.z;
    tgemm<0, true, false, true>(
        g_w16 + (size_t)3 * CH * CH, CH,
        g_ot + (size_t)b * HW * CH, CH,
        CH, 1.f, bo, nullptr, x + (size_t)b * SFE, HW,
        out + (size_t)b * SFE, nullptr, HW);
}

// ================= fused GroupNorm + transpose + fp16 =================
__global__ __launch_bounds__(256) void gnx_kernel(
    const float* __restrict__ x, const float* __restrict__ gamma,
    const float* __restrict__ beta)
{
    const int bg = blockIdx.x;                 // b*32 + g
    const int b = bg >> 5, g = bg & 31;
    const size_t base = (size_t)bg * 16 * HW;
    const int n = 16 * HW;
    const int t = threadIdx.x;

    const float4* xv = (const float4*)(x + base);
    float s = 0.f, ss = 0.f;
    for (int i = t; i < n / 4; i += 256) {
        float4 v = xv[i];
        s  += v.x + v.y + v.z + v.w;
        ss += v.x*v.x + v.y*v.y + v.z*v.z + v.w*v.w;
    }
    __shared__ float sh[64];
    #pragma unroll
    for (int o = 16; o > 0; o >>= 1) {
        s  += __shfl_xor_sync(~0u, s, o);
        ss += __shfl_xor_sync(~0u, ss, o);
    }
    const int warp = t >> 5, lane = t & 31;
    if (lane == 0) { sh[warp] = s; sh[32 + warp] = ss; }
    __syncthreads();
    if (warp == 0) {
        float a = (lane < 8) ? sh[lane] : 0.f;
        float bb = (lane < 8) ? sh[32 + lane] : 0.f;
        #pragma unroll
        for (int o = 4; o > 0; o >>= 1) {
            a  += __shfl_xor_sync(~0u, a, o);
            bb += __shfl_xor_sync(~0u, bb, o);
        }
        if (lane == 0) { sh[0] = a; sh[1] = bb; }
    }
    __syncthreads();
    const float mean = sh[0] / n;
    const float var  = sh[1] / n - mean * mean;
    const float inv  = rsqrtf(var + 1e-6f);
    const int gbase = g * 16;

    const int tc8 = (t >> 7) * 8;
    const int ti  = t & 127;
    float ga[8], be[8];
    #pragma unroll
    for (int q = 0; q < 8; q++) {
        ga[q] = gamma[gbase + tc8 + q] * inv;
        be[q] = beta[gbase + tc8 + q];
    }
    __shared__ float ts[16][129];
    for (int tile = 0; tile < 32; tile++) {
        const int i0 = tile * 128;
        #pragma unroll
        for (int j = 0; j < 8; j++) {
            const int idx = t + 256 * j;
            const int c = idx >> 7, i = idx & 127;
            ts[c][i] = x[base + (size_t)c * HW + i0 + i];
        }
        __syncthreads();
        uint4 hv;
        uint32_t* hw_ = (uint32_t*)&hv;
        #pragma unroll
        for (int q2 = 0; q2 < 4; q2++) {
            const float v0 = (ts[tc8 + q2*2    ][ti] - mean) * ga[q2*2]     + be[q2*2];
            const float v1 = (ts[tc8 + q2*2 + 1][ti] - mean) * ga[q2*2 + 1] + be[q2*2 + 1];
            hw_[q2] = pack2h(__float2half(v0), __float2half(v1));
        }
        *(uint4*)(g_xnT + ((size_t)b * HW + i0 + ti) * CH + gbase + tc8) = hv;
        __syncthreads();
    }
}

// ================= weight convert =================
__global__ __launch_bounds__(256) void wconv_kernel(
    const float* __restrict__ wq, const float* __restrict__ wk,
    const float* __restrict__ wv, const float* __restrict__ wo)
{
    const size_t idx = (size_t)blockIdx.x * 256 + threadIdx.x;
    const int which = (int)(idx >> 18);
    const size_t off = idx & ((1 << 18) - 1);
    const float* w = (which == 0) ? wq : (which == 1) ? wk : (which == 2) ? wv : wo;
    g_w16[idx] = __float2half(w[off]);
}

// ================= softmax: fp16 in -> fp16 out =================
__global__ __launch_bounds__(256) void softmax_kernel()
{
    const size_t row = blockIdx.x;
    const uint2* pv = (const uint2*)(g_s16 + row * HW);
    __half* ph = g_P16 + row * HW;
    const int t = threadIdx.x;
    float v[4][4];
    float mx = -1e30f;
    #pragma unroll
    for (int j = 0; j < 4; j++) {
        uint2 u = pv[t + 256 * j];
        __half2 a = *(__half2*)&u.x, b = *(__half2*)&u.y;
        float2 fa = __half22float2(a), fb = __half22float2(b);
        v[j][0] = fa.x; v[j][1] = fa.y; v[j][2] = fb.x; v[j][3] = fb.y;
        mx = fmaxf(mx, fmaxf(fmaxf(v[j][0], v[j][1]), fmaxf(v[j][2], v[j][3])));
    }
    __shared__ float sh[8];
    #pragma unroll
    for (int o = 16; o > 0; o >>= 1) mx = fmaxf(mx, __shfl_xor_sync(~0u, mx, o));
    if ((t & 31) == 0) sh[t >> 5] = mx;
    __syncthreads();
    const float m0 = fmaxf(fmaxf(fmaxf(sh[0], sh[1]), fmaxf(sh[2], sh[3])),
                           fmaxf(fmaxf(sh[4], sh[5]), fmaxf(sh[6], sh[7])));
    __syncthreads();
    float sum = 0.f;
    #pragma unroll
    for (int j = 0; j < 4; j++) {
        #pragma unroll
        for (int q = 0; q < 4; q++) {
            v[j][q] = __expf(v[j][q] - m0);
            sum += v[j][q];
        }
    }
    #pragma unroll
    for (int o = 16; o > 0; o >>= 1) sum += __shfl_xor_sync(~0u, sum, o);
    if ((t & 31) == 0) sh[t >> 5] = sum;
    __syncthreads();
    const float tot = sh[0]+sh[1]+sh[2]+sh[3]+sh[4]+sh[5]+sh[6]+sh[7];
    const float inv = 1.f / tot;
    #pragma unroll
    for (int j = 0; j < 4; j++) {
        const int eo = (t + 256 * j) * 4;
        uint2 hv = { pack2h(__float2half(v[j][0] * inv), __float2half(v[j][1] * inv)),
                     pack2h(__float2half(v[j][2] * inv), __float2half(v[j][3] * inv)) };
        *(uint2*)(ph + eo) = hv;
    }
}

// ============================================================
extern "C" void kernel_launch(void* const* d_in, const int* in_sizes, int n_in,
                              void* d_out, int out_size)
{
    const float* x   = (const float*)d_in[0];
    const float* gnw = (const float*)d_in[1];
    const float* gnb = (const float*)d_in[2];
    const float* wq  = (const float*)d_in[3];
    const float* bq  = (const float*)d_in[4];
    const float* wk  = (const float*)d_in[5];
    const float* bk  = (const float*)d_in[6];
    const float* wv  = (const float*)d_in[7];
    const float* bv  = (const float*)d_in[8];
    const float* wo  = (const float*)d_in[9];
    const float* bo  = (const float*)d_in[10];
    float* out = (float*)d_out;

    cudaFuncSetAttribute(tg_qk,    cudaFuncAttributeMaxDynamicSharedMemorySize, SM_BYTES);
    cudaFuncSetAttribute(tg_v,     cudaFuncAttributeMaxDynamicSharedMemorySize, SM_BYTES);
    cudaFuncSetAttribute(tg_score, cudaFuncAttributeMaxDynamicSharedMemorySize, SM_BYTES);
    cudaFuncSetAttribute(tg_av,    cudaFuncAttributeMaxDynamicSharedMemorySize, SM_BYTES);
    cudaFuncSetAttribute(tg_out,   cudaFuncAttributeMaxDynamicSharedMemorySize, SM_BYTES);

    gnx_kernel<<<BATCH * NG, 256>>>(x, gnw, gnb);

    wconv_kernel<<<4 * CH * CH / 256, 256>>>(wq, wk, wv, wo);

    dim3 gqk(CH / 256, HW / 128, BATCH * 2);     // (2, 32, 8)
    tg_qk<<<gqk, THREADS, SM_BYTES>>>(bq, bk);

    dim3 gv(HW / 256, CH / 128, BATCH);          // (16, 4, 4)
    tg_v<<<gv, THREADS, SM_BYTES>>>(bv);

    dim3 gs(HW / 256, HW / 128, BATCH);          // (16, 32, 4)
    tg_score<<<gs, THREADS, SM_BYTES>>>();

    softmax_kernel<<<BATCH * HW, 256>>>();

    dim3 ga(CH / 256, HW / 128, BATCH);          // (2, 32, 4)
    tg_av<<<ga, THREADS, SM_BYTES>>>();

    dim3 go(HW / 256, CH / 128, BATCH);          // (16, 4, 4)
    tg_out<<<go, THREADS, SM_BYTES>>>(bo, x, out);
}